// round 14
// baseline (speedup 1.0000x reference)
#include <cuda_runtime.h>
#include <cuda_fp16.h>
#include <math.h>
#include <stdint.h>

#define Bn    16384
#define Dn    1024
#define Hn    512
#define En    16
#define KSEL  2
#define NSLOT (Bn * KSEL)

#define EPSF  2.2204460492503131e-16f

// ---------------- device scratch ----------------
__device__ int   g_counts[En];
__device__ int   g_offsets[En];
__device__ int   g_cursor[En];
__device__ int   g_total_tiles;
__device__ int   g_tile_ctr;
__device__ int   g_slot_row[NSLOT];
__device__ float g_slot_gate[NSLOT];
__device__ int   g_row_slot[NSLOT];
__device__ int   g_expert_of[NSLOT];
__device__ float g_gate_of[NSLOT];
__device__ float g_ys[(size_t)NSLOT * Hn];            // 64 MB (fp32)
__device__ __half g_xh[(size_t)Bn * Dn];              // 32 MB (x fp16)
__device__ __half g_wt[(size_t)En * Hn * Dn];         // 16 MB  [E][H][D] fp16

// ---------------- helpers ----------------
__device__ __forceinline__ uint32_t smem_u32(const void* p) {
    uint32_t a;
    asm("{ .reg .u64 t; cvta.to.shared.u64 t, %1; cvt.u32.u64 %0, t; }" : "=r"(a) : "l"(p));
    return a;
}
#define SW128(o) ((o) ^ (((o) >> 3) & 0x70))

__device__ __forceinline__ void cp16(uint32_t dst, const void* src) {
    asm volatile("cp.async.cg.shared.global [%0], [%1], 16;" :: "r"(dst), "l"(src) : "memory");
}
#define CP_COMMIT() asm volatile("cp.async.commit_group;" ::: "memory")
#define CP_WAIT1()  asm volatile("cp.async.wait_group 1;" ::: "memory")

__device__ __forceinline__ void ldsm4(uint32_t* r, uint32_t tile_base, int row0,
                                      int kbyte, int lane) {
    const uint32_t off = (uint32_t)((row0 + (lane & 15)) * 128 + kbyte + ((lane >> 4) * 16));
    const uint32_t addr = tile_base + SW128(off);
    asm volatile("ldmatrix.sync.aligned.m8n8.x4.shared.b16 {%0,%1,%2,%3}, [%4];"
                 : "=r"(r[0]), "=r"(r[1]), "=r"(r[2]), "=r"(r[3]) : "r"(addr));
}

__device__ __forceinline__ void mma16816(float* c, const uint32_t* a,
                                         uint32_t b0, uint32_t b1) {
    asm volatile(
        "mma.sync.aligned.m16n8k16.row.col.f32.f16.f16.f32 "
        "{%0,%1,%2,%3}, {%4,%5,%6,%7}, {%8,%9}, {%0,%1,%2,%3};"
        : "+f"(c[0]), "+f"(c[1]), "+f"(c[2]), "+f"(c[3])
        : "r"(a[0]), "r"(a[1]), "r"(a[2]), "r"(a[3]), "r"(b0), "r"(b1));
}

// ---------------- kernel 0: zero counts ----------------
__global__ void k_init() {
    int t = threadIdx.x;
    if (t < En) g_counts[t] = 0;
}

// ---------------- fused prep: router (blocks 0..511) + convert_w (512..4607) --
// Router body: 4 rows/warp, identical to round-11 (bit-identical gates).
// Convert_w body: 64d x 32h transpose tile with half2 stores, identical to r11.
#define ROUTER_BLOCKS 512

__global__ void __launch_bounds__(256) k_prep(const float* __restrict__ x,
                                              const float* __restrict__ wr,
                                              const float* __restrict__ w) {
    if (blockIdx.x < ROUTER_BLOCKS) {
        // ---------------- router ----------------
        const int warp = threadIdx.x >> 5;
        const int lane = threadIdx.x & 31;
        const int row0 = (blockIdx.x * 8 + warp) * 4;   // 4 rows per warp

        float acc[4][En];
#pragma unroll
        for (int r = 0; r < 4; r++)
#pragma unroll
            for (int e = 0; e < En; e++) acc[r][e] = 0.f;

        const float* xr = x + (size_t)row0 * Dn;
        __half* xo = g_xh + (size_t)row0 * Dn;

        for (int d = lane; d < Dn; d += 32) {
            const float4* w4 = (const float4*)(wr + (size_t)d * En);
            const float4 w0 = w4[0], w1 = w4[1], w2 = w4[2], w3 = w4[3];
#pragma unroll
            for (int r = 0; r < 4; r++) {
                const float xv = xr[r * Dn + d];
                xo[r * Dn + d] = __float2half(xv);
                acc[r][0]  += xv * w0.x; acc[r][1]  += xv * w0.y;
                acc[r][2]  += xv * w0.z; acc[r][3]  += xv * w0.w;
                acc[r][4]  += xv * w1.x; acc[r][5]  += xv * w1.y;
                acc[r][6]  += xv * w1.z; acc[r][7]  += xv * w1.w;
                acc[r][8]  += xv * w2.x; acc[r][9]  += xv * w2.y;
                acc[r][10] += xv * w2.z; acc[r][11] += xv * w2.w;
                acc[r][12] += xv * w3.x; acc[r][13] += xv * w3.y;
                acc[r][14] += xv * w3.z; acc[r][15] += xv * w3.w;
            }
        }
#pragma unroll
        for (int off = 16; off > 0; off >>= 1) {
#pragma unroll
            for (int r = 0; r < 4; r++)
#pragma unroll
                for (int e = 0; e < En; e++)
                    acc[r][e] += __shfl_xor_sync(0xffffffffu, acc[r][e], off);
        }

        if (lane < 4) {
            const int row = row0 + lane;
            float v1 = -INFINITY; int i1 = 0;
#pragma unroll
            for (int e = 0; e < En; e++) { if (acc[lane][e] > v1) { v1 = acc[lane][e]; i1 = e; } }
            float v2 = -INFINITY; int i2 = 0;
#pragma unroll
            for (int e = 0; e < En; e++) { if (e != i1 && acc[lane][e] > v2) { v2 = acc[lane][e]; i2 = e; } }
            const float e2 = expf(v2 - v1);
            const float inv = 1.0f / (1.0f + e2);
            g_expert_of[row * 2 + 0] = i1;
            g_expert_of[row * 2 + 1] = i2;
            g_gate_of  [row * 2 + 0] = inv;
            g_gate_of  [row * 2 + 1] = e2 * inv;
            atomicAdd(&g_counts[i1], 1);
            atomicAdd(&g_counts[i2], 1);
        }
    } else {
        // ---------------- convert_w ----------------
        __shared__ float t[32][65];                 // [h][d]
        const int b  = blockIdx.x - ROUTER_BLOCKS;  // 0..4095
        const int bx = b & 15;                      // d-tile
        const int by = (b >> 4) & 15;               // h-tile
        const int e  = b >> 8;                      // expert
        const int d0 = bx * 64;
        const int h0 = by * 32;
        const int tx = threadIdx.x & 31;
        const int ty = threadIdx.x >> 5;

        for (int j = ty; j < 64; j += 8)            // j = d index within tile
            t[tx][j] = w[((size_t)e * Dn + d0 + j) * Hn + h0 + tx];
        __syncthreads();
        for (int j = ty; j < 32; j += 8) {          // j = h index within tile
            __half2 v = __floats2half2_rn(t[j][2 * tx], t[j][2 * tx + 1]);
            const size_t o = ((size_t)e * Hn + h0 + j) * Dn + d0 + 2 * tx;
            *(__half2*)&g_wt[o] = v;
        }
    }
}

// ---------------- kernel 2: scan + tile count ----------------
__global__ void k_scan() {
    if (threadIdx.x == 0) {
        int s = 0, nt = 0;
        for (int e = 0; e < En; e++) {
            g_offsets[e] = s;
            g_cursor[e]  = s;
            nt += (g_counts[e] + 127) >> 7;
            s += g_counts[e];
        }
        g_total_tiles = nt * 4;    // x4 h-tiles, h fastest
        g_tile_ctr = 0;
    }
}

// ---------------- kernel 3: scatter (block-aggregated atomics) ----------------
__global__ void k_scatter() {
    __shared__ int bcnt[En];
    __shared__ int bbase[En];
    const int tid = threadIdx.x;
    const int row = blockIdx.x * blockDim.x + tid;

    if (tid < En) bcnt[tid] = 0;
    __syncthreads();

    int e0 = 0, e1 = 0, idx0 = 0, idx1 = 0;
    if (row < Bn) {
        e0 = g_expert_of[row * 2 + 0];
        e1 = g_expert_of[row * 2 + 1];
        idx0 = atomicAdd(&bcnt[e0], 1);
        idx1 = atomicAdd(&bcnt[e1], 1);
    }
    __syncthreads();
    if (tid < En) bbase[tid] = atomicAdd(&g_cursor[tid], bcnt[tid]);
    __syncthreads();

    if (row < Bn) {
        const int s0 = bbase[e0] + idx0;
        const int s1 = bbase[e1] + idx1;
        g_slot_row [s0] = row;
        g_slot_row [s1] = row;
        g_slot_gate[s0] = g_gate_of[row * 2 + 0];
        g_slot_gate[s1] = g_gate_of[row * 2 + 1];
        g_row_slot[row * 2 + 0] = s0;
        g_row_slot[row * 2 + 1] = s1;
    }
}

// ---------------- kernel 4: persistent grouped warp-MMA GEMM -----------------
// BM=128, BN=128, BK=64. 8 warps (2M x 4N), warp tile 64x32.
// 3-stage cp.async pipeline, 1 sync/chunk, 2 CTAs/SM, atomic work stealing.
#define BM 128
#define BN 128
#define BK 64
#define NCHUNK (Dn / BK)          // 16
#define PERSIST_CTAS 304           // 2 per SM x 152 SMs

#define STAGE_BYTES 32768          // A 16K | B 16K
#define A_OFF  0
#define B_OFF  16384
#define CTRL_OFF (3 * STAGE_BYTES)                 // 98304
#define SMEM_BYTES (CTRL_OFF + 2048 + 1024)

__global__ __launch_bounds__(256, 2) void k_gemm() {
    extern __shared__ char smem_raw[];
    const uint32_t sb_raw = smem_u32(smem_raw);
    const uint32_t sb = (sb_raw + 1023u) & ~1023u;
    char* smem = smem_raw + (sb - sb_raw);

    const int tid  = threadIdx.x;
    const int wid  = tid >> 5;
    const int lane = tid & 31;

    int*   srow  = (int*)(smem + CTRL_OFF);
    float* sgate = (float*)(smem + CTRL_OFF + 512);
    int*   meta  = (int*)(smem + CTRL_OFF + 1024);

    const int total = g_total_tiles;
    const int wm = (wid >> 2) * 64;
    const int wn = (wid & 3) * 32;
    static const int bi0[4] = {0, 1, 4, 5};
    static const int bi1[4] = {2, 3, 6, 7};

    for (;;) {
        __syncthreads();   // previous tile fully done with smem ctrl + tiles
        if (tid == 0) {
            const int t = atomicAdd(&g_tile_ctr, 1);
            meta[3] = t;
            if (t < total) {
                const int rt = t >> 2;         // row tile
                int acc = 0, fe = 0, ti = 0;
                for (int e = 0; e < En; e++) {
                    const int nt = (g_counts[e] + BM - 1) / BM;
                    if (rt < acc + nt) { fe = e; ti = rt - acc; break; }
                    acc += nt;
                }
                meta[0] = fe;
                meta[1] = g_offsets[fe] + ti * BM;
                const int rem = g_counts[fe] - ti * BM;
                meta[2] = rem < BM ? rem : BM;
            }
        }
        __syncthreads();
        const int t = meta[3];
        if (t >= total) break;
        const int e     = meta[0];
        const int start = meta[1];
        const int m     = meta[2];
        const int hbase = (t & 3) * BN;

        if (tid < BM) {
            const int slot = (tid < m) ? start + tid : start;
            srow[tid]  = g_slot_row[slot];
            sgate[tid] = (tid < m) ? g_slot_gate[start + tid] : 0.f;
        }
        __syncthreads();

        const __half* wt = g_wt + ((size_t)e * Hn + hbase) * Dn;
        const __half* ax[4];
        const __half* bw[4];
        uint32_t aoff[4];
#pragma unroll
        for (int j = 0; j < 4; j++) {
            const int u = tid + j * 256;
            const int r = u >> 3, c = u & 7;
            ax[j] = g_xh + (size_t)srow[r] * Dn + c * 8;
            bw[j] = wt + (size_t)r * Dn + c * 8;
            aoff[j] = SW128((uint32_t)(r * 128 + c * 16));
        }

#define LOAD_CHUNK(cc) do {                                                    \
    const int s_  = (cc) % 3;                                                  \
    const int kk_ = (cc) * BK;                                                 \
    const uint32_t base_ = sb + s_ * STAGE_BYTES;                              \
    _Pragma("unroll")                                                          \
    for (int j = 0; j < 4; j++) {                                              \
        cp16(base_ + A_OFF + aoff[j], ax[j] + kk_);                            \
        cp16(base_ + B_OFF + aoff[j], bw[j] + kk_);                            \
    }                                                                          \
} while (0)

        float acc[4][4][4];
#pragma unroll
        for (int i = 0; i < 4; i++)
#pragma unroll
            for (int j = 0; j < 4; j++)
#pragma unroll
                for (int q = 0; q < 4; q++) acc[i][j][q] = 0.f;

        LOAD_CHUNK(0); CP_COMMIT();
        LOAD_CHUNK(1); CP_COMMIT();

        for (int ch = 0; ch < NCHUNK; ch++) {
            CP_WAIT1();
            __syncthreads();
            if (ch + 2 < NCHUNK) LOAD_CHUNK(ch + 2);
            CP_COMMIT();

            const uint32_t base = sb + (ch % 3) * STAGE_BYTES;
#pragma unroll
            for (int ks = 0; ks < 4; ks++) {
                const int kbyte = ks * 32;
                uint32_t ah[16], bv[8];
#pragma unroll
                for (int i = 0; i < 4; i++)
                    ldsm4(ah + i * 4, base + A_OFF, wm + i * 16, kbyte, lane);
                ldsm4(bv,     base + B_OFF, wn,      kbyte, lane);
                ldsm4(bv + 4, base + B_OFF, wn + 16, kbyte, lane);

#pragma unroll
                for (int i = 0; i < 4; i++) {
#pragma unroll
                    for (int j = 0; j < 4; j++)
                        mma16816(acc[i][j], ah + i * 4, bv[bi0[j]], bv[bi1[j]]);
                }
            }
        }

        // epilogue: ys[slot][h] = gate * exp(acc)
#pragma unroll
        for (int i = 0; i < 4; i++) {
            const int r0 = wm + i * 16 + (lane >> 2);
            const int r1 = r0 + 8;
            const float g0 = sgate[r0];
            const float g1 = sgate[r1];
            float* d0 = g_ys + (size_t)(start + r0) * Hn + hbase + wn + (lane & 3) * 2;
            float* d1 = g_ys + (size_t)(start + r1) * Hn + hbase + wn + (lane & 3) * 2;
#pragma unroll
            for (int j = 0; j < 4; j++) {
                if (r0 < m) {
                    float2 o;
                    o.x = g0 * expf(acc[i][j][0]);
                    o.y = g0 * expf(acc[i][j][1]);
                    *(float2*)(d0 + j * 8) = o;
                }
                if (r1 < m) {
                    float2 o;
                    o.x = g1 * expf(acc[i][j][2]);
                    o.y = g1 * expf(acc[i][j][3]);
                    *(float2*)(d1 + j * 8) = o;
                }
            }
        }
    }
}

// ---------------- kernel 5: combine ----------------
__global__ void k_combine(float* __restrict__ out) {
    const size_t i = (size_t)blockIdx.x * blockDim.x + threadIdx.x;
    if (i >= (size_t)Bn * Hn / 4) return;
    const int row = (int)(i / (Hn / 4));
    const int seg = (int)(i % (Hn / 4));
    const int s1 = g_row_slot[row * 2 + 0];
    const int s2 = g_row_slot[row * 2 + 1];
    const float4 a = *(const float4*)&g_ys[(size_t)s1 * Hn + seg * 4];
    const float4 b = *(const float4*)&g_ys[(size_t)s2 * Hn + seg * 4];
    float4 o;
    float c;
    c = a.x + b.x; if (c == 0.f) c = EPSF; o.x = logf(c);
    c = a.y + b.y; if (c == 0.f) c = EPSF; o.y = logf(c);
    c = a.z + b.z; if (c == 0.f) c = EPSF; o.z = logf(c);
    c = a.w + b.w; if (c == 0.f) c = EPSF; o.w = logf(c);
    ((float4*)out)[i] = o;
}

// ---------------- launch ----------------
extern "C" void kernel_launch(void* const* d_in, const int* in_sizes, int n_in,
                              void* d_out, int out_size) {
    const float* x  = (const float*)d_in[0];
    const float* wr = (const float*)d_in[1];
    const float* we = (const float*)d_in[2];
    float* out = (float*)d_out;

    cudaFuncSetAttribute(k_gemm, cudaFuncAttributeMaxDynamicSharedMemorySize, SMEM_BYTES);

    k_init<<<1, 32>>>();
    k_prep<<<ROUTER_BLOCKS + (Dn / 64) * (Hn / 32) * En, 256>>>(x, wr, we);
    k_scan<<<1, 32>>>();
    k_scatter<<<Bn / 256, 256>>>();
    k_gemm<<<PERSIST_CTAS, 256, SMEM_BYTES>>>();
    k_combine<<<(Bn * Hn / 4 + 255) / 256, 256>>>(out);
}

// round 15
// speedup vs baseline: 1.1491x; 1.1491x over previous
#include <cuda_runtime.h>
#include <cuda_fp16.h>
#include <math.h>
#include <stdint.h>

#define Bn    16384
#define Dn    1024
#define Hn    512
#define En    16
#define KSEL  2
#define NSLOT (Bn * KSEL)

#define EPSF  2.2204460492503131e-16f

// ---------------- device scratch ----------------
__device__ int   g_counts[En];
__device__ int   g_offsets[En];
__device__ int   g_cursor[En];
__device__ int   g_total_tiles;
__device__ int   g_tile_ctr;
__device__ int   g_slot_row[NSLOT];
__device__ float g_slot_gate[NSLOT];
__device__ int   g_row_slot[NSLOT];
__device__ int   g_expert_of[NSLOT];
__device__ float g_gate_of[NSLOT];
__device__ float g_ys[(size_t)NSLOT * Hn];            // 64 MB (fp32)
__device__ __half g_xh[(size_t)Bn * Dn];              // 32 MB (x fp16)
__device__ __half g_wt[(size_t)En * Hn * Dn];         // 16 MB  [E][H][D] fp16

// ---------------- helpers ----------------
__device__ __forceinline__ uint32_t smem_u32(const void* p) {
    uint32_t a;
    asm("{ .reg .u64 t; cvta.to.shared.u64 t, %1; cvt.u32.u64 %0, t; }" : "=r"(a) : "l"(p));
    return a;
}
#define SW128(o) ((o) ^ (((o) >> 3) & 0x70))

__device__ __forceinline__ void cp16(uint32_t dst, const void* src) {
    asm volatile("cp.async.cg.shared.global [%0], [%1], 16;" :: "r"(dst), "l"(src) : "memory");
}
#define CP_COMMIT() asm volatile("cp.async.commit_group;" ::: "memory")
#define CP_WAIT1()  asm volatile("cp.async.wait_group 1;" ::: "memory")

__device__ __forceinline__ void ldsm4(uint32_t* r, uint32_t tile_base, int row0,
                                      int kbyte, int lane) {
    const uint32_t off = (uint32_t)((row0 + (lane & 15)) * 128 + kbyte + ((lane >> 4) * 16));
    const uint32_t addr = tile_base + SW128(off);
    asm volatile("ldmatrix.sync.aligned.m8n8.x4.shared.b16 {%0,%1,%2,%3}, [%4];"
                 : "=r"(r[0]), "=r"(r[1]), "=r"(r[2]), "=r"(r[3]) : "r"(addr));
}

__device__ __forceinline__ void mma16816(float* c, const uint32_t* a,
                                         uint32_t b0, uint32_t b1) {
    asm volatile(
        "mma.sync.aligned.m16n8k16.row.col.f32.f16.f16.f32 "
        "{%0,%1,%2,%3}, {%4,%5,%6,%7}, {%8,%9}, {%0,%1,%2,%3};"
        : "+f"(c[0]), "+f"(c[1]), "+f"(c[2]), "+f"(c[3])
        : "r"(a[0]), "r"(a[1]), "r"(a[2]), "r"(a[3]), "r"(b0), "r"(b1));
}

// ---------------- kernel 0: zero counts ----------------
__global__ void k_init() {
    int t = threadIdx.x;
    if (t < En) g_counts[t] = 0;
}

// ---------------- kernel 1: router, 4 rows/warp (round-11 champion) ----------
__global__ void __launch_bounds__(256) k_router(const float* __restrict__ x,
                                                const float* __restrict__ wr) {
    const int warp = threadIdx.x >> 5;
    const int lane = threadIdx.x & 31;
    const int row0 = (blockIdx.x * 8 + warp) * 4;   // 4 rows per warp

    float acc[4][En];
#pragma unroll
    for (int r = 0; r < 4; r++)
#pragma unroll
        for (int e = 0; e < En; e++) acc[r][e] = 0.f;

    const float* xr = x + (size_t)row0 * Dn;
    __half* xo = g_xh + (size_t)row0 * Dn;

    for (int d = lane; d < Dn; d += 32) {
        const float4* w4 = (const float4*)(wr + (size_t)d * En);
        const float4 w0 = w4[0], w1 = w4[1], w2 = w4[2], w3 = w4[3];
#pragma unroll
        for (int r = 0; r < 4; r++) {
            const float xv = xr[r * Dn + d];
            xo[r * Dn + d] = __float2half(xv);
            acc[r][0]  += xv * w0.x; acc[r][1]  += xv * w0.y;
            acc[r][2]  += xv * w0.z; acc[r][3]  += xv * w0.w;
            acc[r][4]  += xv * w1.x; acc[r][5]  += xv * w1.y;
            acc[r][6]  += xv * w1.z; acc[r][7]  += xv * w1.w;
            acc[r][8]  += xv * w2.x; acc[r][9]  += xv * w2.y;
            acc[r][10] += xv * w2.z; acc[r][11] += xv * w2.w;
            acc[r][12] += xv * w3.x; acc[r][13] += xv * w3.y;
            acc[r][14] += xv * w3.z; acc[r][15] += xv * w3.w;
        }
    }
#pragma unroll
    for (int off = 16; off > 0; off >>= 1) {
#pragma unroll
        for (int r = 0; r < 4; r++)
#pragma unroll
            for (int e = 0; e < En; e++)
                acc[r][e] += __shfl_xor_sync(0xffffffffu, acc[r][e], off);
    }

    if (lane < 4) {
        const int row = row0 + lane;
        float v1 = -INFINITY; int i1 = 0;
#pragma unroll
        for (int e = 0; e < En; e++) { if (acc[lane][e] > v1) { v1 = acc[lane][e]; i1 = e; } }
        float v2 = -INFINITY; int i2 = 0;
#pragma unroll
        for (int e = 0; e < En; e++) { if (e != i1 && acc[lane][e] > v2) { v2 = acc[lane][e]; i2 = e; } }
        const float e2 = expf(v2 - v1);
        const float inv = 1.0f / (1.0f + e2);
        g_expert_of[row * 2 + 0] = i1;
        g_expert_of[row * 2 + 1] = i2;
        g_gate_of  [row * 2 + 0] = inv;
        g_gate_of  [row * 2 + 1] = e2 * inv;
        atomicAdd(&g_counts[i1], 1);
        atomicAdd(&g_counts[i2], 1);
    }
}

// ---------------- kernel 2: scan + tile count ----------------
__global__ void k_scan() {
    if (threadIdx.x == 0) {
        int s = 0, nt = 0;
        for (int e = 0; e < En; e++) {
            g_offsets[e] = s;
            g_cursor[e]  = s;
            nt += (g_counts[e] + 127) >> 7;
            s += g_counts[e];
        }
        g_total_tiles = nt * 4;    // x4 h-tiles, h fastest
        g_tile_ctr = 0;
    }
}

// ---------------- kernel 3: scatter (block-aggregated atomics) ----------------
__global__ void k_scatter() {
    __shared__ int bcnt[En];
    __shared__ int bbase[En];
    const int tid = threadIdx.x;
    const int row = blockIdx.x * blockDim.x + tid;

    if (tid < En) bcnt[tid] = 0;
    __syncthreads();

    int e0 = 0, e1 = 0, idx0 = 0, idx1 = 0;
    if (row < Bn) {
        e0 = g_expert_of[row * 2 + 0];
        e1 = g_expert_of[row * 2 + 1];
        idx0 = atomicAdd(&bcnt[e0], 1);
        idx1 = atomicAdd(&bcnt[e1], 1);
    }
    __syncthreads();
    if (tid < En) bbase[tid] = atomicAdd(&g_cursor[tid], bcnt[tid]);
    __syncthreads();

    if (row < Bn) {
        const int s0 = bbase[e0] + idx0;
        const int s1 = bbase[e1] + idx1;
        g_slot_row [s0] = row;
        g_slot_row [s1] = row;
        g_slot_gate[s0] = g_gate_of[row * 2 + 0];
        g_slot_gate[s1] = g_gate_of[row * 2 + 1];
        g_row_slot[row * 2 + 0] = s0;
        g_row_slot[row * 2 + 1] = s1;
    }
}

// ---------------- kernel 3c: transpose weights, half2 stores ------------------
__global__ void k_convert_w(const float* __restrict__ w) {
    __shared__ float t[32][65];                 // [h][d]
    const int e  = blockIdx.z;
    const int d0 = blockIdx.x * 64;
    const int h0 = blockIdx.y * 32;
    const int tx = threadIdx.x, ty = threadIdx.y;

    for (int j = ty; j < 64; j += 8)            // j = d index within tile
        t[tx][j] = w[((size_t)e * Dn + d0 + j) * Hn + h0 + tx];
    __syncthreads();
    for (int j = ty; j < 32; j += 8) {          // j = h index within tile
        __half2 v = __floats2half2_rn(t[j][2 * tx], t[j][2 * tx + 1]);
        const size_t o = ((size_t)e * Hn + h0 + j) * Dn + d0 + 2 * tx;
        *(__half2*)&g_wt[o] = v;
    }
}

// ---------------- kernel 4: persistent grouped warp-MMA GEMM -----------------
// BM=128, BN=128, BK=64. 8 warps (2M x 4N), warp tile 64x32.
// 3-stage cp.async pipeline, 1 sync/chunk, 2 CTAs/SM, atomic work stealing.
#define BM 128
#define BN 128
#define BK 64
#define NCHUNK (Dn / BK)          // 16
#define PERSIST_CTAS 304           // 2 per SM x 152 SMs

#define STAGE_BYTES 32768          // A 16K | B 16K
#define A_OFF  0
#define B_OFF  16384
#define CTRL_OFF (3 * STAGE_BYTES)                 // 98304
#define SMEM_BYTES (CTRL_OFF + 2048 + 1024)

__global__ __launch_bounds__(256, 2) void k_gemm() {
    extern __shared__ char smem_raw[];
    const uint32_t sb_raw = smem_u32(smem_raw);
    const uint32_t sb = (sb_raw + 1023u) & ~1023u;
    char* smem = smem_raw + (sb - sb_raw);

    const int tid  = threadIdx.x;
    const int wid  = tid >> 5;
    const int lane = tid & 31;

    int*   srow  = (int*)(smem + CTRL_OFF);
    float* sgate = (float*)(smem + CTRL_OFF + 512);
    int*   meta  = (int*)(smem + CTRL_OFF + 1024);

    const int total = g_total_tiles;
    const int wm = (wid >> 2) * 64;
    const int wn = (wid & 3) * 32;
    static const int bi0[4] = {0, 1, 4, 5};
    static const int bi1[4] = {2, 3, 6, 7};

    for (;;) {
        __syncthreads();   // previous tile fully done with smem ctrl + tiles
        if (tid == 0) {
            const int t = atomicAdd(&g_tile_ctr, 1);
            meta[3] = t;
            if (t < total) {
                const int rt = t >> 2;         // row tile
                int acc = 0, fe = 0, ti = 0;
                for (int e = 0; e < En; e++) {
                    const int nt = (g_counts[e] + BM - 1) / BM;
                    if (rt < acc + nt) { fe = e; ti = rt - acc; break; }
                    acc += nt;
                }
                meta[0] = fe;
                meta[1] = g_offsets[fe] + ti * BM;
                const int rem = g_counts[fe] - ti * BM;
                meta[2] = rem < BM ? rem : BM;
            }
        }
        __syncthreads();
        const int t = meta[3];
        if (t >= total) break;
        const int e     = meta[0];
        const int start = meta[1];
        const int m     = meta[2];
        const int hbase = (t & 3) * BN;

        if (tid < BM) {
            const int slot = (tid < m) ? start + tid : start;
            srow[tid]  = g_slot_row[slot];
            sgate[tid] = (tid < m) ? g_slot_gate[start + tid] : 0.f;
        }
        __syncthreads();

        const __half* wt = g_wt + ((size_t)e * Hn + hbase) * Dn;
        const __half* ax[4];
        const __half* bw[4];
        uint32_t aoff[4];
#pragma unroll
        for (int j = 0; j < 4; j++) {
            const int u = tid + j * 256;
            const int r = u >> 3, c = u & 7;
            ax[j] = g_xh + (size_t)srow[r] * Dn + c * 8;
            bw[j] = wt + (size_t)r * Dn + c * 8;
            aoff[j] = SW128((uint32_t)(r * 128 + c * 16));
        }

#define LOAD_CHUNK(cc) do {                                                    \
    const int s_  = (cc) % 3;                                                  \
    const int kk_ = (cc) * BK;                                                 \
    const uint32_t base_ = sb + s_ * STAGE_BYTES;                              \
    _Pragma("unroll")                                                          \
    for (int j = 0; j < 4; j++) {                                              \
        cp16(base_ + A_OFF + aoff[j], ax[j] + kk_);                            \
        cp16(base_ + B_OFF + aoff[j], bw[j] + kk_);                            \
    }                                                                          \
} while (0)

        float acc[4][4][4];
#pragma unroll
        for (int i = 0; i < 4; i++)
#pragma unroll
            for (int j = 0; j < 4; j++)
#pragma unroll
                for (int q = 0; q < 4; q++) acc[i][j][q] = 0.f;

        LOAD_CHUNK(0); CP_COMMIT();
        LOAD_CHUNK(1); CP_COMMIT();

        for (int ch = 0; ch < NCHUNK; ch++) {
            CP_WAIT1();
            __syncthreads();
            if (ch + 2 < NCHUNK) LOAD_CHUNK(ch + 2);
            CP_COMMIT();

            const uint32_t base = sb + (ch % 3) * STAGE_BYTES;
#pragma unroll
            for (int ks = 0; ks < 4; ks++) {
                const int kbyte = ks * 32;
                uint32_t ah[16], bv[8];
#pragma unroll
                for (int i = 0; i < 4; i++)
                    ldsm4(ah + i * 4, base + A_OFF, wm + i * 16, kbyte, lane);
                ldsm4(bv,     base + B_OFF, wn,      kbyte, lane);
                ldsm4(bv + 4, base + B_OFF, wn + 16, kbyte, lane);

#pragma unroll
                for (int i = 0; i < 4; i++) {
#pragma unroll
                    for (int j = 0; j < 4; j++)
                        mma16816(acc[i][j], ah + i * 4, bv[bi0[j]], bv[bi1[j]]);
                }
            }
        }

        // epilogue: ys[slot][h] = gate * exp(acc)   (fast intrinsic exp)
#pragma unroll
        for (int i = 0; i < 4; i++) {
            const int r0 = wm + i * 16 + (lane >> 2);
            const int r1 = r0 + 8;
            const float g0 = sgate[r0];
            const float g1 = sgate[r1];
            float* d0 = g_ys + (size_t)(start + r0) * Hn + hbase + wn + (lane & 3) * 2;
            float* d1 = g_ys + (size_t)(start + r1) * Hn + hbase + wn + (lane & 3) * 2;
#pragma unroll
            for (int j = 0; j < 4; j++) {
                if (r0 < m) {
                    float2 o;
                    o.x = g0 * __expf(acc[i][j][0]);
                    o.y = g0 * __expf(acc[i][j][1]);
                    *(float2*)(d0 + j * 8) = o;
                }
                if (r1 < m) {
                    float2 o;
                    o.x = g1 * __expf(acc[i][j][2]);
                    o.y = g1 * __expf(acc[i][j][3]);
                    *(float2*)(d1 + j * 8) = o;
                }
            }
        }
    }
}

// ---------------- kernel 5: combine ----------------
__global__ void k_combine(float* __restrict__ out) {
    const size_t i = (size_t)blockIdx.x * blockDim.x + threadIdx.x;
    if (i >= (size_t)Bn * Hn / 4) return;
    const int row = (int)(i / (Hn / 4));
    const int seg = (int)(i % (Hn / 4));
    const int s1 = g_row_slot[row * 2 + 0];
    const int s2 = g_row_slot[row * 2 + 1];
    const float4 a = *(const float4*)&g_ys[(size_t)s1 * Hn + seg * 4];
    const float4 b = *(const float4*)&g_ys[(size_t)s2 * Hn + seg * 4];
    float4 o;
    float c;
    c = a.x + b.x; if (c == 0.f) c = EPSF; o.x = __logf(c);
    c = a.y + b.y; if (c == 0.f) c = EPSF; o.y = __logf(c);
    c = a.z + b.z; if (c == 0.f) c = EPSF; o.z = __logf(c);
    c = a.w + b.w; if (c == 0.f) c = EPSF; o.w = __logf(c);
    ((float4*)out)[i] = o;
}

// ---------------- launch ----------------
extern "C" void kernel_launch(void* const* d_in, const int* in_sizes, int n_in,
                              void* d_out, int out_size) {
    const float* x  = (const float*)d_in[0];
    const float* wr = (const float*)d_in[1];
    const float* we = (const float*)d_in[2];
    float* out = (float*)d_out;

    cudaFuncSetAttribute(k_gemm, cudaFuncAttributeMaxDynamicSharedMemorySize, SMEM_BYTES);

    k_init<<<1, 32>>>();
    k_router<<<Bn / 32, 256>>>(x, wr);
    k_scan<<<1, 32>>>();
    k_scatter<<<Bn / 256, 256>>>();
    dim3 wgrid(Dn / 64, Hn / 32, En);
    k_convert_w<<<wgrid, dim3(32, 8)>>>(we);
    k_gemm<<<PERSIST_CTAS, 256, SMEM_BYTES>>>();
    k_combine<<<(Bn * Hn / 4 + 255) / 256, 256>>>(out);
}

// round 16
// speedup vs baseline: 1.1870x; 1.0329x over previous
#include <cuda_runtime.h>
#include <cuda_fp16.h>
#include <math.h>
#include <stdint.h>

#define Bn    16384
#define Dn    1024
#define Hn    512
#define En    16
#define KSEL  2
#define NSLOT (Bn * KSEL)

#define EPSF  2.2204460492503131e-16f

// ---------------- device scratch ----------------
__device__ int   g_counts[En];
__device__ int   g_offsets[En];
__device__ int   g_cursor[En];
__device__ int   g_total_tiles;
__device__ int   g_tile_ctr;
__device__ int   g_slot_row[NSLOT];
__device__ float g_slot_gate[NSLOT];
__device__ int   g_row_slot[NSLOT];
__device__ int   g_expert_of[NSLOT];
__device__ float g_gate_of[NSLOT];
__device__ float g_ys[(size_t)NSLOT * Hn];            // 64 MB (fp32)
__device__ __half g_xh[(size_t)Bn * Dn];              // 32 MB (x fp16)
__device__ __half g_wt[(size_t)En * Hn * Dn];         // 16 MB  [E][H][D] fp16

// ---------------- helpers ----------------
__device__ __forceinline__ uint32_t smem_u32(const void* p) {
    uint32_t a;
    asm("{ .reg .u64 t; cvta.to.shared.u64 t, %1; cvt.u32.u64 %0, t; }" : "=r"(a) : "l"(p));
    return a;
}
#define SW128(o) ((o) ^ (((o) >> 3) & 0x70))

__device__ __forceinline__ void cp16(uint32_t dst, const void* src) {
    asm volatile("cp.async.cg.shared.global [%0], [%1], 16;" :: "r"(dst), "l"(src) : "memory");
}
#define CP_COMMIT() asm volatile("cp.async.commit_group;" ::: "memory")
#define CP_WAIT1()  asm volatile("cp.async.wait_group 1;" ::: "memory")

__device__ __forceinline__ void ldsm4(uint32_t* r, uint32_t tile_base, int row0,
                                      int kbyte, int lane) {
    const uint32_t off = (uint32_t)((row0 + (lane & 15)) * 128 + kbyte + ((lane >> 4) * 16));
    const uint32_t addr = tile_base + SW128(off);
    asm volatile("ldmatrix.sync.aligned.m8n8.x4.shared.b16 {%0,%1,%2,%3}, [%4];"
                 : "=r"(r[0]), "=r"(r[1]), "=r"(r[2]), "=r"(r[3]) : "r"(addr));
}

__device__ __forceinline__ void mma16816(float* c, const uint32_t* a,
                                         uint32_t b0, uint32_t b1) {
    asm volatile(
        "mma.sync.aligned.m16n8k16.row.col.f32.f16.f16.f32 "
        "{%0,%1,%2,%3}, {%4,%5,%6,%7}, {%8,%9}, {%0,%1,%2,%3};"
        : "+f"(c[0]), "+f"(c[1]), "+f"(c[2]), "+f"(c[3])
        : "r"(a[0]), "r"(a[1]), "r"(a[2]), "r"(a[3]), "r"(b0), "r"(b1));
}

// ---------------- kernel 0: zero counts ----------------
__global__ void k_init() {
    int t = threadIdx.x;
    if (t < En) g_counts[t] = 0;
}

// ---------------- kernel 1: router, 4 rows/warp (round-11 champion) ----------
__global__ void __launch_bounds__(256) k_router(const float* __restrict__ x,
                                                const float* __restrict__ wr) {
    const int warp = threadIdx.x >> 5;
    const int lane = threadIdx.x & 31;
    const int row0 = (blockIdx.x * 8 + warp) * 4;   // 4 rows per warp

    float acc[4][En];
#pragma unroll
    for (int r = 0; r < 4; r++)
#pragma unroll
        for (int e = 0; e < En; e++) acc[r][e] = 0.f;

    const float* xr = x + (size_t)row0 * Dn;
    __half* xo = g_xh + (size_t)row0 * Dn;

    for (int d = lane; d < Dn; d += 32) {
        const float4* w4 = (const float4*)(wr + (size_t)d * En);
        const float4 w0 = w4[0], w1 = w4[1], w2 = w4[2], w3 = w4[3];
#pragma unroll
        for (int r = 0; r < 4; r++) {
            const float xv = xr[r * Dn + d];
            xo[r * Dn + d] = __float2half(xv);
            acc[r][0]  += xv * w0.x; acc[r][1]  += xv * w0.y;
            acc[r][2]  += xv * w0.z; acc[r][3]  += xv * w0.w;
            acc[r][4]  += xv * w1.x; acc[r][5]  += xv * w1.y;
            acc[r][6]  += xv * w1.z; acc[r][7]  += xv * w1.w;
            acc[r][8]  += xv * w2.x; acc[r][9]  += xv * w2.y;
            acc[r][10] += xv * w2.z; acc[r][11] += xv * w2.w;
            acc[r][12] += xv * w3.x; acc[r][13] += xv * w3.y;
            acc[r][14] += xv * w3.z; acc[r][15] += xv * w3.w;
        }
    }
#pragma unroll
    for (int off = 16; off > 0; off >>= 1) {
#pragma unroll
        for (int r = 0; r < 4; r++)
#pragma unroll
            for (int e = 0; e < En; e++)
                acc[r][e] += __shfl_xor_sync(0xffffffffu, acc[r][e], off);
    }

    if (lane < 4) {
        const int row = row0 + lane;
        float v1 = -INFINITY; int i1 = 0;
#pragma unroll
        for (int e = 0; e < En; e++) { if (acc[lane][e] > v1) { v1 = acc[lane][e]; i1 = e; } }
        float v2 = -INFINITY; int i2 = 0;
#pragma unroll
        for (int e = 0; e < En; e++) { if (e != i1 && acc[lane][e] > v2) { v2 = acc[lane][e]; i2 = e; } }
        const float e2 = expf(v2 - v1);
        const float inv = 1.0f / (1.0f + e2);
        g_expert_of[row * 2 + 0] = i1;
        g_expert_of[row * 2 + 1] = i2;
        g_gate_of  [row * 2 + 0] = inv;
        g_gate_of  [row * 2 + 1] = e2 * inv;
        atomicAdd(&g_counts[i1], 1);
        atomicAdd(&g_counts[i2], 1);
    }
}

// ---------------- kernel 2: scan + tile count (BM=64 row tiles) --------------
__global__ void k_scan() {
    if (threadIdx.x == 0) {
        int s = 0, nt = 0;
        for (int e = 0; e < En; e++) {
            g_offsets[e] = s;
            g_cursor[e]  = s;
            nt += (g_counts[e] + 63) >> 6;
            s += g_counts[e];
        }
        g_total_tiles = nt * 4;    // x4 h-tiles, h fastest
        g_tile_ctr = 0;
    }
}

// ---------------- kernel 3: scatter (block-aggregated atomics) ----------------
__global__ void k_scatter() {
    __shared__ int bcnt[En];
    __shared__ int bbase[En];
    const int tid = threadIdx.x;
    const int row = blockIdx.x * blockDim.x + tid;

    if (tid < En) bcnt[tid] = 0;
    __syncthreads();

    int e0 = 0, e1 = 0, idx0 = 0, idx1 = 0;
    if (row < Bn) {
        e0 = g_expert_of[row * 2 + 0];
        e1 = g_expert_of[row * 2 + 1];
        idx0 = atomicAdd(&bcnt[e0], 1);
        idx1 = atomicAdd(&bcnt[e1], 1);
    }
    __syncthreads();
    if (tid < En) bbase[tid] = atomicAdd(&g_cursor[tid], bcnt[tid]);
    __syncthreads();

    if (row < Bn) {
        const int s0 = bbase[e0] + idx0;
        const int s1 = bbase[e1] + idx1;
        g_slot_row [s0] = row;
        g_slot_row [s1] = row;
        g_slot_gate[s0] = g_gate_of[row * 2 + 0];
        g_slot_gate[s1] = g_gate_of[row * 2 + 1];
        g_row_slot[row * 2 + 0] = s0;
        g_row_slot[row * 2 + 1] = s1;
    }
}

// ---------------- kernel 3c: transpose weights, half2 stores ------------------
__global__ void k_convert_w(const float* __restrict__ w) {
    __shared__ float t[32][65];                 // [h][d]
    const int e  = blockIdx.z;
    const int d0 = blockIdx.x * 64;
    const int h0 = blockIdx.y * 32;
    const int tx = threadIdx.x, ty = threadIdx.y;

    for (int j = ty; j < 64; j += 8)            // j = d index within tile
        t[tx][j] = w[((size_t)e * Dn + d0 + j) * Hn + h0 + tx];
    __syncthreads();
    for (int j = ty; j < 32; j += 8) {          // j = h index within tile
        __half2 v = __floats2half2_rn(t[j][2 * tx], t[j][2 * tx + 1]);
        const size_t o = ((size_t)e * Hn + h0 + j) * Dn + d0 + 2 * tx;
        *(__half2*)&g_wt[o] = v;
    }
}

// ---------------- kernel 4: persistent grouped warp-MMA GEMM -----------------
// BM=64, BN=128, BK=64. 8 warps (2M x 4N), warp tile 32x32.
// 2-stage cp.async pipeline (load-after-compute), 3 CTAs/SM, work stealing.
#define BM 64
#define BN 128
#define BK 64
#define NCHUNK (Dn / BK)          // 16
#define PERSIST_CTAS 456           // 3 per SM x 152 SMs

#define STAGE_BYTES 24576          // A 8K | B 16K
#define A_OFF  0
#define B_OFF  8192
#define CTRL_OFF (2 * STAGE_BYTES)                 // 49152
#define SMEM_BYTES (CTRL_OFF + 1024 + 1024)

__global__ __launch_bounds__(256, 3) void k_gemm() {
    extern __shared__ char smem_raw[];
    const uint32_t sb_raw = smem_u32(smem_raw);
    const uint32_t sb = (sb_raw + 1023u) & ~1023u;
    char* smem = smem_raw + (sb - sb_raw);

    const int tid  = threadIdx.x;
    const int wid  = tid >> 5;
    const int lane = tid & 31;

    int*   srow  = (int*)(smem + CTRL_OFF);            // 64 ints
    float* sgate = (float*)(smem + CTRL_OFF + 256);    // 64 floats
    int*   meta  = (int*)(smem + CTRL_OFF + 512);

    const int total = g_total_tiles;
    const int wm = (wid >> 2) * 32;    // 0 / 32
    const int wn = (wid & 3) * 32;     // 0..96
    static const int bi0[4] = {0, 1, 4, 5};
    static const int bi1[4] = {2, 3, 6, 7};

    for (;;) {
        __syncthreads();   // previous tile fully done with smem ctrl + tiles
        if (tid == 0) {
            const int t = atomicAdd(&g_tile_ctr, 1);
            meta[3] = t;
            if (t < total) {
                const int rt = t >> 2;         // row tile
                int acc = 0, fe = 0, ti = 0;
                for (int e = 0; e < En; e++) {
                    const int nt = (g_counts[e] + BM - 1) / BM;
                    if (rt < acc + nt) { fe = e; ti = rt - acc; break; }
                    acc += nt;
                }
                meta[0] = fe;
                meta[1] = g_offsets[fe] + ti * BM;
                const int rem = g_counts[fe] - ti * BM;
                meta[2] = rem < BM ? rem : BM;
            }
        }
        __syncthreads();
        const int t = meta[3];
        if (t >= total) break;
        const int e     = meta[0];
        const int start = meta[1];
        const int m     = meta[2];
        const int hbase = (t & 3) * BN;

        if (tid < BM) {
            const int slot = (tid < m) ? start + tid : start;
            srow[tid]  = g_slot_row[slot];
            sgate[tid] = (tid < m) ? g_slot_gate[start + tid] : 0.f;
        }
        __syncthreads();

        const __half* wt = g_wt + ((size_t)e * Hn + hbase) * Dn;
        const __half* ax[2];
        const __half* bw[4];
        uint32_t aoff[2], boff[4];
#pragma unroll
        for (int j = 0; j < 2; j++) {
            const int u = tid + j * 256;       // 0..511 -> A rows 0..63
            const int r = u >> 3, c = u & 7;
            ax[j] = g_xh + (size_t)srow[r] * Dn + c * 8;
            aoff[j] = SW128((uint32_t)(r * 128 + c * 16));
        }
#pragma unroll
        for (int j = 0; j < 4; j++) {
            const int u = tid + j * 256;       // 0..1023 -> B rows 0..127
            const int r = u >> 3, c = u & 7;
            bw[j] = wt + (size_t)r * Dn + c * 8;
            boff[j] = SW128((uint32_t)(r * 128 + c * 16));
        }

#define LOAD_CHUNK(cc) do {                                                    \
    const int s_  = (cc) & 1;                                                  \
    const int kk_ = (cc) * BK;                                                 \
    const uint32_t base_ = sb + s_ * STAGE_BYTES;                              \
    _Pragma("unroll")                                                          \
    for (int j = 0; j < 2; j++)                                                \
        cp16(base_ + A_OFF + aoff[j], ax[j] + kk_);                            \
    _Pragma("unroll")                                                          \
    for (int j = 0; j < 4; j++)                                                \
        cp16(base_ + B_OFF + boff[j], bw[j] + kk_);                            \
} while (0)

        float acc[2][4][4];
#pragma unroll
        for (int i = 0; i < 2; i++)
#pragma unroll
            for (int j = 0; j < 4; j++)
#pragma unroll
                for (int q = 0; q < 4; q++) acc[i][j][q] = 0.f;

        LOAD_CHUNK(0); CP_COMMIT();
        LOAD_CHUNK(1); CP_COMMIT();

        for (int ch = 0; ch < NCHUNK; ch++) {
            CP_WAIT1();          // groups 0..ch+1 issued; ch complete
            __syncthreads();

            const uint32_t base = sb + (ch & 1) * STAGE_BYTES;
#pragma unroll
            for (int ks = 0; ks < 4; ks++) {
                const int kbyte = ks * 32;
                uint32_t ah[8], bv[8];
                ldsm4(ah,     base + A_OFF, wm,      kbyte, lane);
                ldsm4(ah + 4, base + A_OFF, wm + 16, kbyte, lane);
                ldsm4(bv,     base + B_OFF, wn,      kbyte, lane);
                ldsm4(bv + 4, base + B_OFF, wn + 16, kbyte, lane);

#pragma unroll
                for (int i = 0; i < 2; i++) {
#pragma unroll
                    for (int j = 0; j < 4; j++)
                        mma16816(acc[i][j], ah + i * 4, bv[bi0[j]], bv[bi1[j]]);
                }
            }
            __syncthreads();     // all warps done reading stage ch&1
            if (ch + 2 < NCHUNK) LOAD_CHUNK(ch + 2);
            CP_COMMIT();
        }

        // epilogue: ys[slot][h] = gate * exp(acc)
#pragma unroll
        for (int i = 0; i < 2; i++) {
            const int r0 = wm + i * 16 + (lane >> 2);
            const int r1 = r0 + 8;
            const float g0 = sgate[r0];
            const float g1 = sgate[r1];
            float* d0 = g_ys + (size_t)(start + r0) * Hn + hbase + wn + (lane & 3) * 2;
            float* d1 = g_ys + (size_t)(start + r1) * Hn + hbase + wn + (lane & 3) * 2;
#pragma unroll
            for (int j = 0; j < 4; j++) {
                if (r0 < m) {
                    float2 o;
                    o.x = g0 * __expf(acc[i][j][0]);
                    o.y = g0 * __expf(acc[i][j][1]);
                    *(float2*)(d0 + j * 8) = o;
                }
                if (r1 < m) {
                    float2 o;
                    o.x = g1 * __expf(acc[i][j][2]);
                    o.y = g1 * __expf(acc[i][j][3]);
                    *(float2*)(d1 + j * 8) = o;
                }
            }
        }
    }
}

// ---------------- kernel 5: combine ----------------
__global__ void k_combine(float* __restrict__ out) {
    const size_t i = (size_t)blockIdx.x * blockDim.x + threadIdx.x;
    if (i >= (size_t)Bn * Hn / 4) return;
    const int row = (int)(i / (Hn / 4));
    const int seg = (int)(i % (Hn / 4));
    const int s1 = g_row_slot[row * 2 + 0];
    const int s2 = g_row_slot[row * 2 + 1];
    const float4 a = *(const float4*)&g_ys[(size_t)s1 * Hn + seg * 4];
    const float4 b = *(const float4*)&g_ys[(size_t)s2 * Hn + seg * 4];
    float4 o;
    float c;
    c = a.x + b.x; if (c == 0.f) c = EPSF; o.x = __logf(c);
    c = a.y + b.y; if (c == 0.f) c = EPSF; o.y = __logf(c);
    c = a.z + b.z; if (c == 0.f) c = EPSF; o.z = __logf(c);
    c = a.w + b.w; if (c == 0.f) c = EPSF; o.w = __logf(c);
    ((float4*)out)[i] = o;
}

// ---------------- launch ----------------
extern "C" void kernel_launch(void* const* d_in, const int* in_sizes, int n_in,
                              void* d_out, int out_size) {
    const float* x  = (const float*)d_in[0];
    const float* wr = (const float*)d_in[1];
    const float* we = (const float*)d_in[2];
    float* out = (float*)d_out;

    cudaFuncSetAttribute(k_gemm, cudaFuncAttributeMaxDynamicSharedMemorySize, SMEM_BYTES);

    k_init<<<1, 32>>>();
    k_router<<<Bn / 32, 256>>>(x, wr);
    k_scan<<<1, 32>>>();
    k_scatter<<<Bn / 256, 256>>>();
    dim3 wgrid(Dn / 64, Hn / 32, En);
    k_convert_w<<<wgrid, dim3(32, 8)>>>(we);
    k_gemm<<<PERSIST_CTAS, 256, SMEM_BYTES>>>();
    k_combine<<<(Bn * Hn / 4 + 255) / 256, 256>>>(out);
}